// round 11
// baseline (speedup 1.0000x reference)
#include <cuda_runtime.h>
#include <cuda_fp16.h>

// Problem constants
#define B_TOTAL  2
#define C_IN     32
#define HDIM     64
#define WDIM     64
#define J_TOTAL  4096
#define S_TOTAL  256
#define HID      64
#define C_OUT    32
#define JPB      8       // 1024 blocks -> ~7/SM, single balanced wave
#define SCHUNK   64      // s-chunk staged in smem (16KB as half2)

// Scratch
__device__ __half2 g_Qh[B_TOTAL * S_TOTAL * HID];  // duplicated (q,q) f16x2
__device__ float   g_Qf[B_TOTAL * S_TOTAL * HID];  // f32 for exact SQ
__device__ float   g_SQ[B_TOTAL * HID];            // sum_s Q[b,s,h]

__device__ __forceinline__ __half2 tanh2(__half2 v) {
    unsigned u = *reinterpret_cast<unsigned*>(&v);
    unsigned r;
    asm("tanh.approx.f16x2 %0, %1;" : "=r"(r) : "r"(u));
    return *reinterpret_cast<__half2*>(&r);
}

// ---------- kernel 1: Q[b,s,h], 4-way c-split ----------
__global__ void precompute_q(const float* __restrict__ v,
                             const int* __restrict__ indices,
                             const float* __restrict__ W1,
                             const float* __restrict__ b1) {
    __shared__ float part[256];
    int tid = threadIdx.x;
    int g   = tid >> 6;               // 0..3 (c-group)
    int h   = tid & 63;
    int s   = blockIdx.x;
    int b   = blockIdx.y;
    int idx = indices[s] & (J_TOTAL - 1);

    const float* vb = v + (size_t)b * C_IN * J_TOTAL + idx;
    float p = 0.0f;
#pragma unroll
    for (int cc = 0; cc < 8; cc++) {
        int c = g * 8 + cc;
        p = fmaf(vb[(size_t)c * J_TOTAL], W1[(2 + c) * HID + h], p);
    }
    part[tid] = p;
    __syncthreads();

    if (g == 0) {
        int ix = idx & (WDIM - 1);
        int iy = idx >> 6;
        float sx = ix * (1.0f / 63.0f);
        float sy = iy * (1.0f / 63.0f);
        float acc = b1[h] - sx * W1[h] - sy * W1[HID + h]
                  + part[h] + part[64 + h] + part[128 + h] + part[192 + h];
        int o = (b * S_TOTAL + s) * HID + h;
        g_Qf[o] = acc;
        g_Qh[o] = __float2half2_rn(acc);   // duplicated halves
    }
}

// ---------- kernel 2: SQ[b,h] = sum_s Q (f32 exact) ----------
__global__ void precompute_sq() {
    int h = threadIdx.x;
    int b = blockIdx.x;
    float acc = 0.0f;
    const float* Qb = g_Qf + (size_t)b * S_TOTAL * HID;
#pragma unroll 8
    for (int s = 0; s < S_TOTAL; s++) acc += Qb[s * HID + h];
    g_SQ[b * HID + h] = acc;
}

// ---------- kernel 3: main ----------
// sum_s gelu_tanh(a+q) = 0.5*( S*a + SQ + sum_s t*tanh(v) ),
// v = t*(C1 + C2*t^2), f16x2 (2 j's per instruction).
// 4 s-steps per iteration as 4 INDEPENDENT chains into 2 alternating f16x2
// accumulators (ILP restore vs the serial-pacc version), flushed to f32
// every 4 s (t*tanh >= 0, no cancellation).
__global__ __launch_bounds__(256)
void nystrom_main(const float* __restrict__ W1,
                  const float* __restrict__ W2,
                  const float* __restrict__ b2,
                  float* __restrict__ out) {
    __shared__ __half2 Qs2[SCHUNK * HID];  // 16 KB; overlaid as Gs in epilogue
    __shared__ float W2s[HID * C_OUT];     // 8 KB
    __shared__ float w1x[HID];
    __shared__ float w1y[HID];
    __shared__ float b2s[C_OUT];

    int tid   = threadIdx.x;
    int b     = blockIdx.y;
    int j0    = blockIdx.x * JPB;
    int group = tid >> 6;                  // 0..3
    int h     = tid & 63;

    if (tid < HID) { w1x[tid] = W1[tid]; w1y[tid] = W1[HID + tid]; }
    if (tid >= 64 && tid < 64 + C_OUT) b2s[tid - 64] = b2[tid - 64];
    for (int i = tid; i < HID * C_OUT; i += 256) W2s[i] = W2[i];
    __syncthreads();

    // Each thread owns 2 j's (same h)
    float a[2];
#pragma unroll
    for (int i = 0; i < 2; i++) {
        int j = j0 + group * 2 + i;
        float x = (j & (WDIM - 1)) * (1.0f / 63.0f);
        float y = (j >> 6)         * (1.0f / 63.0f);
        a[i] = fmaf(x, w1x[h], y * w1y[h]);
    }
    __half2 a2 = __floats2half2_rn(a[0], a[1]);   // lo = j0-lane
    const __half2 kC1 = __float2half2_rn(0.7978845608028654f);
    const __half2 kC2 = __float2half2_rn(0.0356774081f);
    const __half2 kZ  = __float2half2_rn(0.0f);

    float acc0 = 0.0f, acc1 = 0.0f;

    const __half2* Qg = g_Qh + (size_t)b * S_TOTAL * HID;
#pragma unroll
    for (int chunk = 0; chunk < S_TOTAL / SCHUNK; chunk++) {
        __syncthreads();  // protect Qs2 overwrite
        for (int i = tid; i < SCHUNK * HID; i += 256)
            Qs2[i] = Qg[chunk * SCHUNK * HID + i];
        __syncthreads();

#pragma unroll
        for (int s4 = 0; s4 < SCHUNK / 4; s4++) {
            // 4 independent gelu-pair chains
            __half2 q0 = Qs2[(s4 * 4 + 0) * HID + h];
            __half2 q1 = Qs2[(s4 * 4 + 1) * HID + h];
            __half2 q2 = Qs2[(s4 * 4 + 2) * HID + h];
            __half2 q3 = Qs2[(s4 * 4 + 3) * HID + h];

            __half2 t0 = __hadd2(a2, q0);
            __half2 t1 = __hadd2(a2, q1);
            __half2 t2 = __hadd2(a2, q2);
            __half2 t3 = __hadd2(a2, q3);

            __half2 v0 = __hmul2(t0, __hfma2(kC2, __hmul2(t0, t0), kC1));
            __half2 v1 = __hmul2(t1, __hfma2(kC2, __hmul2(t1, t1), kC1));
            __half2 v2 = __hmul2(t2, __hfma2(kC2, __hmul2(t2, t2), kC1));
            __half2 v3 = __hmul2(t3, __hfma2(kC2, __hmul2(t3, t3), kC1));

            __half2 th0 = tanh2(v0);
            __half2 th1 = tanh2(v1);
            __half2 th2 = tanh2(v2);
            __half2 th3 = tanh2(v3);

            __half2 pa = __hfma2(t0, th0, kZ);
            __half2 pb = __hfma2(t1, th1, kZ);
            pa = __hfma2(t2, th2, pa);
            pb = __hfma2(t3, th3, pb);

            float2 f = __half22float2(__hadd2(pa, pb));  // flush to f32
            acc0 += f.x;
            acc1 += f.y;
        }
    }

    // sum_s gelu = 0.5*(acc + S*a + SQ)
    float sq = g_SQ[b * HID + h];
    float sums[2];
    sums[0] = 0.5f * (acc0 + fmaf((float)S_TOTAL, a[0], sq));
    sums[1] = 0.5f * (acc1 + fmaf((float)S_TOTAL, a[1], sq));

    // Epilogue
    __syncthreads();
    float* Gs = reinterpret_cast<float*>(Qs2);  // overlay (8*64 floats)
#pragma unroll
    for (int i = 0; i < 2; i++)
        Gs[(group * 2 + i) * HID + h] = sums[i];
    __syncthreads();

    // 256 outputs = 8 j * 32 c, one per thread
    {
        int jj = tid >> 5;
        int c  = tid & 31;
        float sum = 0.0f;
#pragma unroll
        for (int hh = 0; hh < HID; hh++)
            sum = fmaf(Gs[jj * HID + hh], W2s[hh * C_OUT + c], sum);
        out[((size_t)b * C_OUT + c) * J_TOTAL + (j0 + jj)] =
            fmaf(sum, 1.0f / (float)S_TOTAL, b2s[c]);
    }
}

extern "C" void kernel_launch(void* const* d_in, const int* in_sizes, int n_in,
                              void* d_out, int out_size) {
    const float* v       = (const float*)d_in[0];
    const int*   indices = (const int*)d_in[1];
    const float* W1      = (const float*)d_in[2];
    const float* b1      = (const float*)d_in[3];
    const float* W2      = (const float*)d_in[4];
    const float* b2      = (const float*)d_in[5];
    float*       out     = (float*)d_out;

    precompute_q<<<dim3(S_TOTAL, B_TOTAL), 256>>>(v, indices, W1, b1);
    precompute_sq<<<B_TOTAL, HID>>>();
    nystrom_main<<<dim3(J_TOTAL / JPB, B_TOTAL), 256>>>(W1, W2, b2, out);
}

// round 13
// speedup vs baseline: 3.4844x; 3.4844x over previous
#include <cuda_runtime.h>

// Problem constants
#define B_TOTAL  2
#define C_IN     32
#define WDIM     64
#define J_TOTAL  4096
#define S_TOTAL  256
#define HID      64
#define C_OUT    32

// Coefficients: g_C[b][h][10] = {c0..c8, a0}
// G_bh(a0+d) ~= sum_k c_k d^k,  G = sum_s gelu(a + q_s)
__device__ float g_C[B_TOTAL * HID * 10];

// Phi(t) = 0.5*(1+erf(t/sqrt2)) via Abramowitz-Stegun 7.1.26 (abs err ~1.5e-7)
__device__ __forceinline__ float Phi_f(float t) {
    float u  = t * 0.70710678118654752f;
    float au = fabsf(u);
    float k  = __fdividef(1.0f, fmaf(0.3275911f, au, 1.0f));
    float p  = fmaf(fmaf(fmaf(fmaf(1.061405429f, k, -1.453152027f),
                              k,  1.421413741f),
                         k, -0.284496736f),
                    k,  0.254829592f) * k;
    float e  = __expf(-u * u);
    float pe = p * e;
    float w  = (u >= 0.0f) ? (2.0f - pe) : pe;
    return 0.5f * w;
}

// ---------- kernel 1: per-(b,h) Taylor coefficients (degree 8) ----------
__global__ __launch_bounds__(256)
void coeff_kernel(const float* __restrict__ v,
                  const int* __restrict__ indices,
                  const float* __restrict__ W1,
                  const float* __restrict__ b1) {
    __shared__ float red[8][9];
    int s = threadIdx.x;            // 0..255 == S_TOTAL
    int h = blockIdx.x;
    int b = blockIdx.y;

    float w1x = W1[h];
    float w1y = W1[HID + h];
    float a0  = 0.5f * (w1x + w1y);

    int idx = indices[s] & (J_TOTAL - 1);
    int ix  = idx & (WDIM - 1);
    int iy  = idx >> 6;
    float q = b1[h] - (ix * (1.0f / 63.0f)) * w1x - (iy * (1.0f / 63.0f)) * w1y;
    const float* vb = v + (size_t)b * C_IN * J_TOTAL + idx;
#pragma unroll
    for (int c = 0; c < C_IN; c++)
        q = fmaf(vb[(size_t)c * J_TOTAL], W1[(2 + c) * HID + h], q);

    float t  = a0 + q;
    float t2 = t * t;
    float t4 = t2 * t2;
    float t6 = t4 * t2;
    float ph = 0.3989422804014327f * __expf(-0.5f * t2);  // phi(t)
    float PH = Phi_f(t);                                  // Phi(t)

    // c_k = gelu^(k)(t)/k!,  gelu(x)=x*Phi(x), phi' = -x phi
    float c[9];
    c[0] = t * PH;                                        // gelu(t)
    c[1] = fmaf(t, ph, PH);                               // Phi + t phi
    c[2] = (2.0f - t2) * ph * 0.5f;
    c[3] = (t2 - 4.0f) * t * ph * (1.0f / 6.0f);
    c[4] = fmaf(-t4, 1.0f, fmaf(7.0f, t2, -4.0f)) * ph * (1.0f / 24.0f);       // (-t^4+7t^2-4)
    c[5] = fmaf(t4, 1.0f, fmaf(-11.0f, t2, 18.0f)) * t * ph * (1.0f / 120.0f); // (t^5-11t^3+18t)
    c[6] = (-t6 + 16.0f * t4 - 51.0f * t2 + 18.0f) * ph * (1.0f / 720.0f);
    c[7] = (t6 - 22.0f * t4 + 115.0f * t2 - 120.0f) * t * ph * (1.0f / 5040.0f);
    c[8] = (-t6 * t2 + 29.0f * t6 - 225.0f * t4 + 465.0f * t2 - 120.0f) * ph * (1.0f / 40320.0f);

    // warp reduce each coefficient
#pragma unroll
    for (int k = 0; k < 9; k++) {
        float x = c[k];
#pragma unroll
        for (int o = 16; o; o >>= 1)
            x += __shfl_xor_sync(0xffffffff, x, o);
        c[k] = x;
    }
    int lane = s & 31, w = s >> 5;
    if (lane == 0)
#pragma unroll
        for (int k = 0; k < 9; k++) red[w][k] = c[k];
    __syncthreads();

    if (s < 9) {                    // thread k sums coefficient k across 8 warps
        float acc = 0.0f;
#pragma unroll
        for (int w2 = 0; w2 < 8; w2++) acc += red[w2][s];
        g_C[(b * HID + h) * 10 + s] = acc;
    }
    if (s == 9) g_C[(b * HID + h) * 10 + 9] = a0;
}

// ---------- kernel 2: evaluate + W2 contraction ----------
__global__ __launch_bounds__(256)
void eval_kernel(const float* __restrict__ W1,
                 const float* __restrict__ W2,
                 const float* __restrict__ b2,
                 float* __restrict__ out) {
    __shared__ float Gs[32 * HID];     // 8 KB
    __shared__ float W2s[HID * C_OUT]; // 8 KB
    __shared__ float Cs[HID * 10];     // 2.5 KB
    __shared__ float w1xs[HID], w1ys[HID], b2s[C_OUT];

    int tid = threadIdx.x;
    int b   = blockIdx.y;
    int j0  = blockIdx.x * 32;

    for (int i = tid; i < HID * 10; i += 256) Cs[i] = g_C[b * HID * 10 + i];
    for (int i = tid; i < HID * C_OUT; i += 256) W2s[i] = W2[i];
    if (tid < HID) { w1xs[tid] = W1[tid]; w1ys[tid] = W1[HID + tid]; }
    if (tid >= 64 && tid < 64 + C_OUT) b2s[tid - 64] = b2[tid - 64];
    __syncthreads();

    int h  = tid & 63;
    int jg = tid >> 6;                 // 0..3, each owns 8 j's
    float cc[9];
#pragma unroll
    for (int k = 0; k < 9; k++) cc[k] = Cs[h * 10 + k];
    float a0 = Cs[h * 10 + 9];
    float wx = w1xs[h], wy = w1ys[h];

#pragma unroll
    for (int i = 0; i < 8; i++) {
        int j = j0 + jg * 8 + i;
        float x = (j & (WDIM - 1)) * (1.0f / 63.0f);
        float y = (j >> 6)         * (1.0f / 63.0f);
        float d = fmaf(x, wx, y * wy) - a0;
        float p = cc[8];
#pragma unroll
        for (int k = 7; k >= 0; k--) p = fmaf(p, d, cc[k]);
        Gs[(jg * 8 + i) * HID + h] = p;
    }
    __syncthreads();

    // 32 j * 32 c = 1024 outputs, 4 per thread
#pragma unroll
    for (int r = 0; r < 4; r++) {
        int o  = tid + r * 256;
        int jj = o >> 5;
        int c  = o & 31;
        float sum = 0.0f;
#pragma unroll
        for (int hh = 0; hh < HID; hh++)
            sum = fmaf(Gs[jj * HID + hh], W2s[hh * C_OUT + c], sum);
        out[((size_t)b * C_OUT + c) * J_TOTAL + (j0 + jj)] =
            fmaf(sum, 1.0f / (float)S_TOTAL, b2s[c]);
    }
}

extern "C" void kernel_launch(void* const* d_in, const int* in_sizes, int n_in,
                              void* d_out, int out_size) {
    const float* v       = (const float*)d_in[0];
    const int*   indices = (const int*)d_in[1];
    const float* W1      = (const float*)d_in[2];
    const float* b1      = (const float*)d_in[3];
    const float* W2      = (const float*)d_in[4];
    const float* b2      = (const float*)d_in[5];
    float*       out     = (float*)d_out;

    coeff_kernel<<<dim3(HID, B_TOTAL), S_TOTAL>>>(v, indices, W1, b1);
    eval_kernel<<<dim3(J_TOTAL / 32, B_TOTAL), 256>>>(W1, W2, b2, out);
}

// round 14
// speedup vs baseline: 3.6708x; 1.0535x over previous
#include <cuda_runtime.h>

// Problem constants
#define B_TOTAL  2
#define C_IN     32
#define WDIM     64
#define J_TOTAL  4096
#define S_TOTAL  256
#define HID      64
#define C_OUT    32

// Coefficients: g_C[b][h][10] = {c0..c8, a0}
// G_bh(a0+d) ~= sum_k c_k d^k,  G = sum_s gelu(a + q_s)
__device__ float g_C[B_TOTAL * HID * 10];

// Phi(t) = 0.5*(1+erf(t/sqrt2)) via Abramowitz-Stegun 7.1.26 (abs err ~1.5e-7)
__device__ __forceinline__ float Phi_f(float t) {
    float u  = t * 0.70710678118654752f;
    float au = fabsf(u);
    float k  = __fdividef(1.0f, fmaf(0.3275911f, au, 1.0f));
    float p  = fmaf(fmaf(fmaf(fmaf(1.061405429f, k, -1.453152027f),
                              k,  1.421413741f),
                         k, -0.284496736f),
                    k,  0.254829592f) * k;
    float e  = __expf(-u * u);
    float pe = p * e;
    float w  = (u >= 0.0f) ? (2.0f - pe) : pe;
    return 0.5f * w;
}

// ---------- kernel 1: per-(b,h) Taylor coefficients (degree 8) ----------
__global__ __launch_bounds__(256)
void coeff_kernel(const float* __restrict__ v,
                  const int* __restrict__ indices,
                  const float* __restrict__ W1,
                  const float* __restrict__ b1) {
    __shared__ float red[8][9];
    int s = threadIdx.x;            // 0..255 == S_TOTAL
    int h = blockIdx.x;
    int b = blockIdx.y;

    float w1x = W1[h];
    float w1y = W1[HID + h];
    float a0  = 0.5f * (w1x + w1y);

    int idx = indices[s] & (J_TOTAL - 1);
    int ix  = idx & (WDIM - 1);
    int iy  = idx >> 6;
    float q = b1[h] - (ix * (1.0f / 63.0f)) * w1x - (iy * (1.0f / 63.0f)) * w1y;
    const float* vb = v + (size_t)b * C_IN * J_TOTAL + idx;
#pragma unroll
    for (int c = 0; c < C_IN; c++)
        q = fmaf(vb[(size_t)c * J_TOTAL], W1[(2 + c) * HID + h], q);

    float t  = a0 + q;
    float t2 = t * t;
    float t4 = t2 * t2;
    float t6 = t4 * t2;
    float ph = 0.3989422804014327f * __expf(-0.5f * t2);  // phi(t)
    float PH = Phi_f(t);                                  // Phi(t)

    // c_k = gelu^(k)(t)/k!,  gelu(x)=x*Phi(x), phi' = -x phi
    float c[9];
    c[0] = t * PH;                                        // gelu(t)
    c[1] = fmaf(t, ph, PH);                               // Phi + t phi
    c[2] = (2.0f - t2) * ph * 0.5f;
    c[3] = (t2 - 4.0f) * t * ph * (1.0f / 6.0f);
    c[4] = fmaf(-t4, 1.0f, fmaf(7.0f, t2, -4.0f)) * ph * (1.0f / 24.0f);       // (-t^4+7t^2-4)
    c[5] = fmaf(t4, 1.0f, fmaf(-11.0f, t2, 18.0f)) * t * ph * (1.0f / 120.0f); // (t^5-11t^3+18t)
    c[6] = (-t6 + 16.0f * t4 - 51.0f * t2 + 18.0f) * ph * (1.0f / 720.0f);
    c[7] = (t6 - 22.0f * t4 + 115.0f * t2 - 120.0f) * t * ph * (1.0f / 5040.0f);
    c[8] = (-t6 * t2 + 29.0f * t6 - 225.0f * t4 + 465.0f * t2 - 120.0f) * ph * (1.0f / 40320.0f);

    // warp reduce each coefficient
#pragma unroll
    for (int k = 0; k < 9; k++) {
        float x = c[k];
#pragma unroll
        for (int o = 16; o; o >>= 1)
            x += __shfl_xor_sync(0xffffffff, x, o);
        c[k] = x;
    }
    int lane = s & 31, w = s >> 5;
    if (lane == 0)
#pragma unroll
        for (int k = 0; k < 9; k++) red[w][k] = c[k];
    __syncthreads();

    if (s < 9) {                    // thread k sums coefficient k across 8 warps
        float acc = 0.0f;
#pragma unroll
        for (int w2 = 0; w2 < 8; w2++) acc += red[w2][s];
        g_C[(b * HID + h) * 10 + s] = acc;
    }
    if (s == 9) g_C[(b * HID + h) * 10 + 9] = a0;
}

// ---------- kernel 2: evaluate + W2 contraction ----------
__global__ __launch_bounds__(256)
void eval_kernel(const float* __restrict__ W1,
                 const float* __restrict__ W2,
                 const float* __restrict__ b2,
                 float* __restrict__ out) {
    __shared__ float Gs[32 * HID];     // 8 KB
    __shared__ float W2s[HID * C_OUT]; // 8 KB
    __shared__ float Cs[HID * 10];     // 2.5 KB
    __shared__ float w1xs[HID], w1ys[HID], b2s[C_OUT];

    int tid = threadIdx.x;
    int b   = blockIdx.y;
    int j0  = blockIdx.x * 32;

    for (int i = tid; i < HID * 10; i += 256) Cs[i] = g_C[b * HID * 10 + i];
    for (int i = tid; i < HID * C_OUT; i += 256) W2s[i] = W2[i];
    if (tid < HID) { w1xs[tid] = W1[tid]; w1ys[tid] = W1[HID + tid]; }
    if (tid >= 64 && tid < 64 + C_OUT) b2s[tid - 64] = b2[tid - 64];
    __syncthreads();

    int h  = tid & 63;
    int jg = tid >> 6;                 // 0..3, each owns 8 j's
    float cc[9];
#pragma unroll
    for (int k = 0; k < 9; k++) cc[k] = Cs[h * 10 + k];
    float a0 = Cs[h * 10 + 9];
    float wx = w1xs[h], wy = w1ys[h];

#pragma unroll
    for (int i = 0; i < 8; i++) {
        int j = j0 + jg * 8 + i;
        float x = (j & (WDIM - 1)) * (1.0f / 63.0f);
        float y = (j >> 6)         * (1.0f / 63.0f);
        float d = fmaf(x, wx, y * wy) - a0;
        float p = cc[8];
#pragma unroll
        for (int k = 7; k >= 0; k--) p = fmaf(p, d, cc[k]);
        Gs[(jg * 8 + i) * HID + h] = p;
    }
    __syncthreads();

    // 32 j * 32 c = 1024 outputs, 4 per thread
#pragma unroll
    for (int r = 0; r < 4; r++) {
        int o  = tid + r * 256;
        int jj = o >> 5;
        int c  = o & 31;
        float sum = 0.0f;
#pragma unroll
        for (int hh = 0; hh < HID; hh++)
            sum = fmaf(Gs[jj * HID + hh], W2s[hh * C_OUT + c], sum);
        out[((size_t)b * C_OUT + c) * J_TOTAL + (j0 + jj)] =
            fmaf(sum, 1.0f / (float)S_TOTAL, b2s[c]);
    }
}

extern "C" void kernel_launch(void* const* d_in, const int* in_sizes, int n_in,
                              void* d_out, int out_size) {
    const float* v       = (const float*)d_in[0];
    const int*   indices = (const int*)d_in[1];
    const float* W1      = (const float*)d_in[2];
    const float* b1      = (const float*)d_in[3];
    const float* W2      = (const float*)d_in[4];
    const float* b2      = (const float*)d_in[5];
    float*       out     = (float*)d_out;

    coeff_kernel<<<dim3(HID, B_TOTAL), S_TOTAL>>>(v, indices, W1, b1);
    eval_kernel<<<dim3(J_TOTAL / 32, B_TOTAL), 256>>>(W1, W2, b2, out);
}

// round 15
// speedup vs baseline: 3.9469x; 1.0752x over previous
#include <cuda_runtime.h>

// Problem constants
#define B_TOTAL  2
#define C_IN     32
#define WDIM     64
#define J_TOTAL  4096
#define S_TOTAL  256
#define HID      64
#define C_OUT    32
#define JPB      64      // j per eval block: 64x2 = 128 blocks = single wave

// Coefficients: g_C[b][h][10] = {c0..c8, a0}
// G_bh(a0+d) ~= sum_k c_k d^k,  G = sum_s gelu(a + q_s)
__device__ float g_C[B_TOTAL * HID * 10];

// Phi(t) = 0.5*(1+erf(t/sqrt2)) via Abramowitz-Stegun 7.1.26 (abs err ~1.5e-7)
__device__ __forceinline__ float Phi_f(float t) {
    float u  = t * 0.70710678118654752f;
    float au = fabsf(u);
    float k  = __fdividef(1.0f, fmaf(0.3275911f, au, 1.0f));
    float p  = fmaf(fmaf(fmaf(fmaf(1.061405429f, k, -1.453152027f),
                              k,  1.421413741f),
                         k, -0.284496736f),
                    k,  0.254829592f) * k;
    float e  = __expf(-u * u);
    float pe = p * e;
    float w  = (u >= 0.0f) ? (2.0f - pe) : pe;
    return 0.5f * w;
}

// ---------- kernel 1: per-(b,h) Taylor coefficients (degree 8) ----------
__global__ __launch_bounds__(256)
void coeff_kernel(const float* __restrict__ v,
                  const int* __restrict__ indices,
                  const float* __restrict__ W1,
                  const float* __restrict__ b1) {
    __shared__ float red[8][9];
    int s = threadIdx.x;            // 0..255 == S_TOTAL
    int h = blockIdx.x;
    int b = blockIdx.y;

    float w1x = W1[h];
    float w1y = W1[HID + h];
    float a0  = 0.5f * (w1x + w1y);

    int idx = indices[s] & (J_TOTAL - 1);
    int ix  = idx & (WDIM - 1);
    int iy  = idx >> 6;
    float q = b1[h] - (ix * (1.0f / 63.0f)) * w1x - (iy * (1.0f / 63.0f)) * w1y;
    const float* vb = v + (size_t)b * C_IN * J_TOTAL + idx;
#pragma unroll
    for (int c = 0; c < C_IN; c++)
        q = fmaf(vb[(size_t)c * J_TOTAL], W1[(2 + c) * HID + h], q);

    float t  = a0 + q;
    float t2 = t * t;
    float t4 = t2 * t2;
    float t6 = t4 * t2;
    float ph = 0.3989422804014327f * __expf(-0.5f * t2);  // phi(t)
    float PH = Phi_f(t);                                  // Phi(t)

    // c_k = gelu^(k)(t)/k!,  gelu(x)=x*Phi(x), phi' = -x phi
    float c[9];
    c[0] = t * PH;                                        // gelu(t)
    c[1] = fmaf(t, ph, PH);                               // Phi + t phi
    c[2] = (2.0f - t2) * ph * 0.5f;
    c[3] = (t2 - 4.0f) * t * ph * (1.0f / 6.0f);
    c[4] = (-t4 + 7.0f * t2 - 4.0f) * ph * (1.0f / 24.0f);
    c[5] = (t4 - 11.0f * t2 + 18.0f) * t * ph * (1.0f / 120.0f);
    c[6] = (-t6 + 16.0f * t4 - 51.0f * t2 + 18.0f) * ph * (1.0f / 720.0f);
    c[7] = (t6 - 22.0f * t4 + 115.0f * t2 - 120.0f) * t * ph * (1.0f / 5040.0f);
    c[8] = (-t6 * t2 + 29.0f * t6 - 225.0f * t4 + 465.0f * t2 - 120.0f) * ph * (1.0f / 40320.0f);

    // warp reduce each coefficient
#pragma unroll
    for (int k = 0; k < 9; k++) {
        float x = c[k];
#pragma unroll
        for (int o = 16; o; o >>= 1)
            x += __shfl_xor_sync(0xffffffff, x, o);
        c[k] = x;
    }
    int lane = s & 31, w = s >> 5;
    if (lane == 0)
#pragma unroll
        for (int k = 0; k < 9; k++) red[w][k] = c[k];
    __syncthreads();

    if (s < 9) {                    // thread k sums coefficient k across 8 warps
        float acc = 0.0f;
#pragma unroll
        for (int w2 = 0; w2 < 8; w2++) acc += red[w2][s];
        g_C[(b * HID + h) * 10 + s] = acc;
    }
    if (s == 9) g_C[(b * HID + h) * 10 + 9] = a0;
}

// ---------- kernel 2: evaluate + W2 contraction (64 j / block, 1 wave) ----------
__global__ __launch_bounds__(256)
void eval_kernel(const float* __restrict__ W1,
                 const float* __restrict__ W2,
                 const float* __restrict__ b2,
                 float* __restrict__ out) {
    __shared__ float Gs[JPB * 65];     // padded: row stride 65 -> conflict-free j-strided reads
    __shared__ float W2s[HID * C_OUT]; // 8 KB
    __shared__ float Cs[HID * 10];     // 2.5 KB
    __shared__ float w1xs[HID], w1ys[HID], b2s[C_OUT];

    int tid = threadIdx.x;
    int b   = blockIdx.y;
    int j0  = blockIdx.x * JPB;

    for (int i = tid; i < HID * 10; i += 256) Cs[i] = g_C[b * HID * 10 + i];
    for (int i = tid; i < HID * C_OUT; i += 256) W2s[i] = W2[i];
    if (tid < HID) { w1xs[tid] = W1[tid]; w1ys[tid] = W1[HID + tid]; }
    if (tid >= 64 && tid < 64 + C_OUT) b2s[tid - 64] = b2[tid - 64];
    __syncthreads();

    // Horner: h = tid&63, jg = tid>>6 owns 16 j's
    {
        int h  = tid & 63;
        int jg = tid >> 6;
        float cc[9];
#pragma unroll
        for (int k = 0; k < 9; k++) cc[k] = Cs[h * 10 + k];
        float a0 = Cs[h * 10 + 9];
        float wx = w1xs[h], wy = w1ys[h];
#pragma unroll
        for (int i = 0; i < 16; i++) {
            int jj = jg * 16 + i;
            int j  = j0 + jj;
            float x = (j & (WDIM - 1)) * (1.0f / 63.0f);
            float y = (j >> 6)         * (1.0f / 63.0f);
            float d = fmaf(x, wx, y * wy) - a0;
            float p = cc[8];
#pragma unroll
            for (int k = 7; k >= 0; k--) p = fmaf(p, d, cc[k]);
            Gs[jj * 65 + h] = p;
        }
    }
    __syncthreads();

    // Epilogue: thread owns 2 j's (lane-consecutive) x 4 c's.
    // out[b,c,j] = sum_h Gs[j,h]*W2[h,c] / S + b2[c]
    {
        int jlane = tid & 31;          // jA = jlane, jB = jlane+32
        int grp   = tid >> 5;          // 0..7 -> c = grp*4 + k
        float sum[8];
#pragma unroll
        for (int k = 0; k < 8; k++) sum[k] = 0.0f;

        const float* gA = &Gs[jlane * 65];
        const float* gB = &Gs[(jlane + 32) * 65];
#pragma unroll 8
        for (int hh = 0; hh < HID; hh++) {
            float g0 = gA[hh];
            float g1 = gB[hh];
#pragma unroll
            for (int k = 0; k < 4; k++) {
                float w = W2s[hh * C_OUT + grp * 4 + k];   // warp-uniform broadcast
                sum[k]     = fmaf(g0, w, sum[k]);
                sum[4 + k] = fmaf(g1, w, sum[4 + k]);
            }
        }
#pragma unroll
        for (int k = 0; k < 4; k++) {
            int c = grp * 4 + k;
            float base = b2s[c];
            out[((size_t)b * C_OUT + c) * J_TOTAL + j0 + jlane] =
                fmaf(sum[k], 1.0f / (float)S_TOTAL, base);
            out[((size_t)b * C_OUT + c) * J_TOTAL + j0 + jlane + 32] =
                fmaf(sum[4 + k], 1.0f / (float)S_TOTAL, base);
        }
    }
}

extern "C" void kernel_launch(void* const* d_in, const int* in_sizes, int n_in,
                              void* d_out, int out_size) {
    const float* v       = (const float*)d_in[0];
    const int*   indices = (const int*)d_in[1];
    const float* W1      = (const float*)d_in[2];
    const float* b1      = (const float*)d_in[3];
    const float* W2      = (const float*)d_in[4];
    const float* b2      = (const float*)d_in[5];
    float*       out     = (float*)d_out;

    coeff_kernel<<<dim3(HID, B_TOTAL), S_TOTAL>>>(v, indices, W1, b1);
    eval_kernel<<<dim3(J_TOTAL / JPB, B_TOTAL), 256>>>(W1, W2, b2, out);
}